// round 16
// baseline (speedup 1.0000x reference)
#include <cuda_runtime.h>
#include <cuda_fp16.h>
#include <cstdint>
#include <math.h>

#define EPS_SQ 1e-8f

// ---------------- scratch (static device arrays; no allocation) ----------------
__device__ __align__(16) __half d_a1col[26214400];  // im2col A [512*400][128] fp16 (k 81..127 = 0)
__device__ __align__(16) __half d_w1pk[32768];      // w1 packed [2 kc][256 co][64] fp16
__device__ __align__(16) __half d_h1x[52428800];    // [512b][20y][20x][256] fp16
__device__ __align__(16) __half d_w2pk[5308416];    // [81 kxy][256co][256ci] fp16
__device__ __align__(16) float  d_u[4718592];       // u [512][1152][8]
__device__ __align__(16) __half d_uhat_h[94371840]; // u_hat [512][1152][160] fp16

__device__ __forceinline__ uint32_t smem_u32(const void* p) {
    uint32_t a;
    asm("{ .reg .u64 t; cvta.to.shared.u64 t, %1; cvt.u32.u64 %0, t; }" : "=r"(a) : "l"(p));
    return a;
}
#define SW128(x) ((x) ^ (((x) >> 3) & 0x70))

__device__ __forceinline__ void cp_async16(uint32_t dst, const void* src) {
    asm volatile("cp.async.cg.shared.global [%0], [%1], 16;" :: "r"(dst), "l"(src));
}
#define CP_COMMIT() asm volatile("cp.async.commit_group;" ::: "memory")
#define CP_WAIT1()  asm volatile("cp.async.wait_group 1;" ::: "memory")
#define CP_WAIT0()  asm volatile("cp.async.wait_group 0;" ::: "memory")

#define LDSM4(r, a) asm volatile( \
    "ldmatrix.sync.aligned.m8n8.x4.shared.b16 {%0,%1,%2,%3}, [%4];" \
    : "=r"((r)[0]), "=r"((r)[1]), "=r"((r)[2]), "=r"((r)[3]) : "r"(a))

#define MMA16816(c, a, b0, b1) asm volatile( \
    "mma.sync.aligned.m16n8k16.row.col.f32.f16.f16.f32 " \
    "{%0,%1,%2,%3}, {%4,%5,%6,%7}, {%8,%9}, {%0,%1,%2,%3};" \
    : "+f"((c)[0]), "+f"((c)[1]), "+f"((c)[2]), "+f"((c)[3]) \
    : "r"((a)[0]), "r"((a)[1]), "r"((a)[2]), "r"((a)[3]), "r"(b0), "r"(b1))

// ---------------- im2col for conv1: A[(b*400+pos)][128], split over 2 pos-halves ----
__global__ __launch_bounds__(256) void im2col_kernel(const float* __restrict__ in)
{
    int b   = blockIdx.x;
    int tid = threadIdx.x;
    __shared__ __half xs[784];
    for (int t = tid; t < 784; t += 256) xs[t] = __float2half_rn(in[b * 784 + t]);
    __syncthreads();

    int k  = tid & 127;
    int p0 = (tid >> 7) + blockIdx.y * 200;
    int pend = blockIdx.y * 200 + 200;
    bool valid = (k < 81);
    int ky = k / 9, kx = k - ky * 9;
    __half zero = __float2half_rn(0.f);
    __half* dst = d_a1col + (size_t)b * 51200 + k;
    for (int pos = p0; pos < pend; pos += 2) {
        int oy = pos / 20, ox = pos - oy * 20;
        dst[pos * 128] = valid ? xs[(oy + ky) * 28 + ox + kx] : zero;
    }
}

// ---------------- pack conv1 weights: [2 kc][256 co][64] fp16 ----------------
__global__ __launch_bounds__(256) void packw1_kernel(const float* __restrict__ w1)
{
    int idx = blockIdx.x * 256 + threadIdx.x;
    if (idx >= 32768) return;
    int j  = idx & 63;
    int co = (idx >> 6) & 255;
    int kc = idx >> 14;
    int k  = kc * 64 + j;
    d_w1pk[idx] = (k < 81) ? __float2half_rn(w1[co * 81 + k]) : __float2half_rn(0.f);
}

// ---------------- conv1 as HMMA GEMM: D[204800,256] = A[.,128] x B[128,256] ----
__global__ void __launch_bounds__(256, 2) conv1_mma_kernel(const float* __restrict__ b1)
{
    extern __shared__ __align__(1024) char smem[];
    uint32_t sb = smem_u32(smem);
    int tid  = threadIdx.x;
    int lane = tid & 31, wid = tid >> 5;
    int mtile = blockIdx.x >> 1, nhalf = blockIdx.x & 1;
    int wm = wid & 3, wn = wid >> 2;

    int apart = tid & 7;
    uint32_t dstoff[4];
    const __half* asrc[4];
    const __half* bsrc[4];
#pragma unroll
    for (int k = 0; k < 4; k++) {
        int r = (tid >> 3) + 32 * k;
        dstoff[k] = SW128((uint32_t)(r * 128 + apart * 16));
        asrc[k] = d_a1col + (size_t)(mtile * 128 + r) * 128 + apart * 8;
        bsrc[k] = d_w1pk + (nhalf * 128 + r) * 64 + apart * 8;
    }

    int rA = wm * 32 + ((lane >> 3) & 1) * 8 + (lane & 7);
    uint32_t aoff0 = (uint32_t)(rA * 128);
    uint32_t keyA = rA & 7, colA = (lane >> 4) & 1;
    int rB = wn * 64 + ((lane >> 4) & 1) * 8 + (lane & 7);
    uint32_t boff0 = (uint32_t)(rB * 128);
    uint32_t keyB = rB & 7, colB = (lane >> 3) & 1;

    float acc[2][8][4];
#pragma unroll
    for (int s = 0; s < 2; s++)
#pragma unroll
        for (int nf = 0; nf < 8; nf++)
#pragma unroll
            for (int e = 0; e < 4; e++) acc[s][nf][e] = 0.f;

#pragma unroll
    for (int kc = 0; kc < 2; kc++) {
        uint32_t abuf = sb + kc * 32768;
        uint32_t bbuf = abuf + 16384;
#pragma unroll
        for (int k = 0; k < 4; k++) {
            cp_async16(abuf + dstoff[k], asrc[k] + kc * 64);
            cp_async16(bbuf + dstoff[k], bsrc[k] + kc * 16384);
        }
        CP_COMMIT();
    }
    CP_WAIT0();
    __syncthreads();

#pragma unroll
    for (int kc = 0; kc < 2; kc++) {
        uint32_t abuf = sb + kc * 32768;
        uint32_t bbuf = abuf + 16384;
#pragma unroll
        for (int kk = 0; kk < 4; kk++) {
            uint32_t a0[4], a1[4];
            uint32_t ca = (((uint32_t)(kk * 2) + colA) ^ keyA) << 4;
            LDSM4(a0, abuf + aoff0 + ca);
            LDSM4(a1, abuf + aoff0 + 2048 + ca);
            uint32_t cb = (((uint32_t)(kk * 2) + colB) ^ keyB) << 4;
#pragma unroll
            for (int p = 0; p < 4; p++) {
                uint32_t bfr[4];
                LDSM4(bfr, bbuf + boff0 + p * 2048 + cb);
                MMA16816(acc[0][2 * p],     a0, bfr[0], bfr[1]);
                MMA16816(acc[0][2 * p + 1], a0, bfr[2], bfr[3]);
                MMA16816(acc[1][2 * p],     a1, bfr[0], bfr[1]);
                MMA16816(acc[1][2 * p + 1], a1, bfr[2], bfr[3]);
            }
        }
    }

    int co0 = nhalf * 128 + wn * 64 + (lane & 3) * 2;
    float bias0[8], bias1[8];
#pragma unroll
    for (int nf = 0; nf < 8; nf++) {
        float2 bv = *(const float2*)(b1 + co0 + nf * 8);
        bias0[nf] = bv.x; bias1[nf] = bv.y;
    }
#pragma unroll
    for (int s = 0; s < 2; s++) {
#pragma unroll
        for (int h = 0; h < 2; h++) {
            int m = mtile * 128 + wm * 32 + s * 16 + (lane >> 2) + h * 8;
            __half* ptr = d_h1x + (size_t)m * 256 + co0;
#pragma unroll
            for (int nf = 0; nf < 8; nf++) {
                float o0 = fmaxf(acc[s][nf][h * 2 + 0] + bias0[nf], 0.f);
                float o1 = fmaxf(acc[s][nf][h * 2 + 1] + bias1[nf], 0.f);
                *(__half2*)(ptr + nf * 8) = __floats2half2_rn(o0, o1);
            }
        }
    }
}

// ---------------- pack conv2 weights: [81][co 256][256 ci] fp16 ----------------
__global__ __launch_bounds__(256) void packw2_kernel(const float* __restrict__ w2)
{
    int idx = blockIdx.x * 256 + threadIdx.x;
    if (idx >= 81 * 256 * 256) return;
    int ci   = idx & 255;
    int co   = (idx >> 8) & 255;
    int kidx = idx >> 16;
    int ky = kidx / 9, kx = kidx - ky * 9;
    float v = w2[((size_t)(co * 256 + ci) * 81) + ky * 9 + kx];
    d_w2pk[(size_t)kidx * 65536 + co * 256 + ci] = __float2half_rn(v);
}

// ---------------- conv2 as HMMA implicit GEMM ----------------
// grid = 288 (144 M-tiles x 2 N-halves), 256 threads (8 warps of 32x64),
// 2 blocks/SM. 324 K-chunks of 64; 3-buffer pipeline, ONE sync per chunk,
// stage issued BEFORE compute (2-chunk prefetch distance).
__global__ void __launch_bounds__(256, 2) conv2_mma_kernel(const float* __restrict__ b2)
{
    extern __shared__ __align__(1024) char smem[];
    uint32_t sb = smem_u32(smem);
    int tid  = threadIdx.x;
    int lane = tid & 31, wid = tid >> 5;
    int mtile = blockIdx.x >> 1, nhalf = blockIdx.x & 1;
    int wm = wid & 3, wn = wid >> 2;

    int apart = tid & 7;
    uint32_t dstoff[4];
    int rowbase[4];
    size_t bsrcoff[4];
#pragma unroll
    for (int k = 0; k < 4; k++) {
        int r = (tid >> 3) + 32 * k;
        dstoff[k] = SW128((uint32_t)(r * 128 + apart * 16));
        int m = mtile * 128 + r;
        int bb = m / 36, pos = m - bb * 36;
        int oy = pos / 6, ox = pos - oy * 6;
        rowbase[k] = bb * 400 + oy * 40 + ox * 2;
        bsrcoff[k] = (size_t)(nhalf * 128 + r) * 256 + apart * 8;
    }

    int rA = wm * 32 + ((lane >> 3) & 1) * 8 + (lane & 7);
    uint32_t aoff0 = (uint32_t)(rA * 128);
    uint32_t keyA = rA & 7, colA = (lane >> 4) & 1;
    int rB = wn * 64 + ((lane >> 4) & 1) * 8 + (lane & 7);
    uint32_t boff0 = (uint32_t)(rB * 128);
    uint32_t keyB = rB & 7, colB = (lane >> 3) & 1;

    float acc[2][8][4];
#pragma unroll
    for (int s = 0; s < 2; s++)
#pragma unroll
        for (int nf = 0; nf < 8; nf++)
#pragma unroll
            for (int e = 0; e < 4; e++) acc[s][nf][e] = 0.f;

    // stage chunk c into buffer buf (A 128x64 = 16KB, B 128x64 = 16KB)
    auto stage = [&](int c, int buf) {
        uint32_t abuf = sb + buf * 32768;
        uint32_t bbuf = abuf + 16384;
        int kidx = c >> 2, cc = c & 3;
        int ky = kidx / 9;
        int koff = ky * 20 + (kidx - ky * 9);
        int ci0 = cc << 6;
        const __half* bsrc = d_w2pk + (size_t)kidx * 65536 + ci0;
#pragma unroll
        for (int k = 0; k < 4; k++) {
            const void* as = d_h1x + (size_t)(rowbase[k] + koff) * 256 + ci0 + apart * 8;
            cp_async16(abuf + dstoff[k], as);
            cp_async16(bbuf + dstoff[k], bsrc + bsrcoff[k]);
        }
    };

    stage(0, 0); CP_COMMIT();
    stage(1, 1); CP_COMMIT();

    int buf = 0;
    for (int c = 0; c < 324; c++) {
        if (c + 2 < 324) { CP_WAIT1(); } else { CP_WAIT0(); }
        __syncthreads();

        // issue next-next stage FIRST: cp.async gets a full compute-chunk of cover
        if (c + 2 < 324) {
            int bn = buf + 2; if (bn >= 3) bn -= 3;
            stage(c + 2, bn);
            CP_COMMIT();
        }

        uint32_t abuf = sb + buf * 32768;
        uint32_t bbuf = abuf + 16384;
#pragma unroll
        for (int kk = 0; kk < 4; kk++) {
            uint32_t a0[4], a1[4];
            uint32_t ca = (((uint32_t)(kk * 2) + colA) ^ keyA) << 4;
            LDSM4(a0, abuf + aoff0 + ca);
            LDSM4(a1, abuf + aoff0 + 2048 + ca);
            uint32_t cb = (((uint32_t)(kk * 2) + colB) ^ keyB) << 4;
#pragma unroll
            for (int p = 0; p < 4; p++) {
                uint32_t bfr[4];
                LDSM4(bfr, bbuf + boff0 + p * 2048 + cb);
                MMA16816(acc[0][2 * p],     a0, bfr[0], bfr[1]);
                MMA16816(acc[0][2 * p + 1], a0, bfr[2], bfr[3]);
                MMA16816(acc[1][2 * p],     a1, bfr[0], bfr[1]);
                MMA16816(acc[1][2 * p + 1], a1, bfr[2], bfr[3]);
            }
        }

        buf = (buf == 2) ? 0 : buf + 1;
    }

    // ---- epilogue: bias add + scattered float2 stores into transposed u ----
    int co0 = nhalf * 128 + wn * 64 + (lane & 3) * 2;
    float bias0[8], bias1[8];
#pragma unroll
    for (int nf = 0; nf < 8; nf++) {
        float2 bv = *(const float2*)(b2 + co0 + nf * 8);
        bias0[nf] = bv.x; bias1[nf] = bv.y;
    }
#pragma unroll
    for (int s = 0; s < 2; s++) {
        int m0 = mtile * 128 + wm * 32 + s * 16 + (lane >> 2);
#pragma unroll
        for (int h = 0; h < 2; h++) {
            int m = m0 + h * 8;
            int bb = m / 36, pos = m - bb * 36;
            int oy = pos / 6, ox = pos - oy * 6;
            float* ptr = d_u + (size_t)bb * 9216 + ox * 1536 + oy * 256 + co0;
#pragma unroll
            for (int nf = 0; nf < 8; nf++) {
                float2 o;
                o.x = acc[s][nf][h * 2 + 0] + bias0[nf];
                o.y = acc[s][nf][h * 2 + 1] + bias1[nf];
                *(float2*)(ptr + nf * 8) = o;
            }
        }
    }
}

// ---------------- u_hat kernel: block = capsule i, W loaded once, fp16 out ----
__global__ __launch_bounds__(160) void uhat_kernel(const float* __restrict__ capW)
{
    int i   = blockIdx.x;
    int tid = threadIdx.x;
    __shared__ __align__(16) float Ws[1280];
    __shared__ __align__(16) float us[4096];

    for (int t = tid; t < 1280; t += 160) Ws[t] = capW[(size_t)i * 1280 + t];
    for (int t = tid; t < 4096; t += 160) {
        int b = t >> 3, p = t & 7;
        us[t] = d_u[(size_t)b * 9216 + i * 8 + p];
    }
    __syncthreads();

    float wreg[8];
    int off = (tid >> 4) * 128 + (tid & 15);
#pragma unroll
    for (int p = 0; p < 8; p++) wreg[p] = Ws[off + p * 16];

    __half* dst = d_uhat_h + (size_t)i * 160 + tid;
#pragma unroll 4
    for (int b = 0; b < 512; b++) {
        const float4* uq = (const float4*)&us[b * 8];
        float4 x0 = uq[0], x1 = uq[1];
        float a = x0.x * wreg[0] + x0.y * wreg[1] + x0.z * wreg[2] + x0.w * wreg[3]
                + x1.x * wreg[4] + x1.y * wreg[5] + x1.z * wreg[6] + x1.w * wreg[7];
        dst[(size_t)b * 184320] = __float2half_rn(a);
    }
}

// ---------------- fused dynamic routing: 3 uhat passes (fp16), per-batch block ----
__global__ __launch_bounds__(640) void caps_kernel(float* __restrict__ outp)
{
    extern __shared__ float smf[];
    float* bs   = smf;             // [1152*10]
    float* red  = bs + 11520;      // [20*160]
    float* sv   = red + 3200;      // [160]
    float* coef = sv + 160;        // [16]

    int tid  = threadIdx.x;
    int b    = blockIdx.x;
    int lane = tid & 31, warp = tid >> 5, hl = lane >> 4;
    const __half* ub = d_uhat_h + (size_t)b * 184320;

    float sacc[5];

    auto reduce_squash = [&](float scale) {
        __syncthreads();
#pragma unroll
        for (int r = 0; r < 5; r++) red[warp * 160 + lane + 32 * r] = sacc[r];
        __syncthreads();
        if (tid < 160) {
            float s = 0.f;
#pragma unroll
            for (int w = 0; w < 20; w++) s += red[w * 160 + tid];
            sv[tid] = s * scale;
        }
        __syncthreads();
        if (tid < 10) {
            float sq = 0.f;
#pragma unroll
            for (int q = 0; q < 16; q++) { float v = sv[tid * 16 + q]; sq += v * v; }
            coef[tid] = sq * rsqrtf(sq + EPS_SQ) / (1.f + sq);
        }
        __syncthreads();
        if (tid < 160) sv[tid] = coef[tid >> 4] * sv[tid];
        __syncthreads();
    };

    // ---- pass 0: c = 1/10 uniform (i-loop unrolled x2) ----
#pragma unroll
    for (int r = 0; r < 5; r++) sacc[r] = 0.f;
    {
        int i = warp;
        for (; i + 20 < 1152; i += 40) {
            const __half* up0 = ub + (size_t)i * 160;
            const __half* up1 = ub + (size_t)(i + 20) * 160;
#pragma unroll
            for (int r = 0; r < 5; r++)
                sacc[r] += __half2float(up0[lane + 32 * r]) + __half2float(up1[lane + 32 * r]);
        }
        if (i < 1152) {
            const __half* up = ub + (size_t)i * 160;
#pragma unroll
            for (int r = 0; r < 5; r++) sacc[r] += __half2float(up[lane + 32 * r]);
        }
    }
    reduce_squash(0.1f);

    // ---- passes 1, 2: fused b-update + softmax + s-accumulate (unrolled x2) ----
#pragma unroll 1
    for (int pass = 1; pass <= 2; pass++) {
        float vreg[5];
#pragma unroll
        for (int r = 0; r < 5; r++) vreg[r] = sv[lane + 32 * r];
#pragma unroll
        for (int r = 0; r < 5; r++) sacc[r] = 0.f;

        auto body = [&](int i) {
            const __half* up = ub + (size_t)i * 160;
            float uh[5], d[5];
#pragma unroll
            for (int r = 0; r < 5; r++) uh[r] = __half2float(up[lane + 32 * r]);
#pragma unroll
            for (int r = 0; r < 5; r++) d[r] = uh[r] * vreg[r];
#pragma unroll
            for (int mk = 8; mk; mk >>= 1)
#pragma unroll
                for (int r = 0; r < 5; r++) d[r] += __shfl_xor_sync(0xffffffffu, d[r], mk);

            float bnew[5];
            if (pass == 1) {
#pragma unroll
                for (int r = 0; r < 5; r++) bnew[r] = d[r];
                if ((lane & 15) == 0) {
#pragma unroll
                    for (int r = 0; r < 5; r++) bs[i * 10 + 2 * r + hl] = bnew[r];
                }
            } else {
#pragma unroll
                for (int r = 0; r < 5; r++) bnew[r] = bs[i * 10 + 2 * r + hl] + d[r];
            }

            float m1 = bnew[0];
#pragma unroll
            for (int r = 1; r < 5; r++) m1 = fmaxf(m1, bnew[r]);
            m1 = fmaxf(m1, __shfl_xor_sync(0xffffffffu, m1, 16));
            float e[5], ss = 0.f;
#pragma unroll
            for (int r = 0; r < 5; r++) { e[r] = __expf(bnew[r] - m1); ss += e[r]; }
            ss += __shfl_xor_sync(0xffffffffu, ss, 16);
            float inv = 1.f / ss;
#pragma unroll
            for (int r = 0; r < 5; r++) sacc[r] += e[r] * inv * uh[r];
        };

        int i = warp;
        for (; i + 20 < 1152; i += 40) { body(i); body(i + 20); }
        if (i < 1152) body(i);

        reduce_squash(1.0f);
    }

    if (tid < 160) outp[b * 160 + tid] = sv[tid];
}

// ---------------- launch ----------------
extern "C" void kernel_launch(void* const* d_in, const int* in_sizes, int n_in,
                              void* d_out, int out_size)
{
    const float* inp = (const float*)d_in[0];
    const float* w1  = (const float*)d_in[1];
    const float* b1  = (const float*)d_in[2];
    const float* w2  = (const float*)d_in[3];
    const float* b2  = (const float*)d_in[4];
    const float* cw  = (const float*)d_in[5];
    float* outp = (float*)d_out;

    im2col_kernel<<<dim3(512, 2), 256>>>(inp);
    packw1_kernel<<<128, 256>>>(w1);
    packw2_kernel<<<(81 * 256 * 256 + 255) / 256, 256>>>(w2);

    cudaFuncSetAttribute(conv1_mma_kernel, cudaFuncAttributeMaxDynamicSharedMemorySize, 65536);
    conv1_mma_kernel<<<3200, 256, 65536>>>(b1);

    cudaFuncSetAttribute(conv2_mma_kernel, cudaFuncAttributeMaxDynamicSharedMemorySize, 98304);
    conv2_mma_kernel<<<288, 256, 98304>>>(b2);

    uhat_kernel<<<1152, 160>>>(cw);

    const int caps_smem = (11520 + 3200 + 160 + 16) * 4;   // 59584 B
    cudaFuncSetAttribute(caps_kernel, cudaFuncAttributeMaxDynamicSharedMemorySize, caps_smem);
    caps_kernel<<<512, 640, caps_smem>>>(outp);
}

// round 17
// speedup vs baseline: 1.0413x; 1.0413x over previous
#include <cuda_runtime.h>
#include <cuda_fp16.h>
#include <cstdint>
#include <math.h>

#define EPS_SQ 1e-8f

// ---------------- scratch (static device arrays; no allocation) ----------------
__device__ __align__(16) __half d_a1col[26214400];  // im2col A [512*400][128] fp16 (k 81..127 = 0)
__device__ __align__(16) __half d_w1pk[32768];      // w1 packed [2 kc][256 co][64] fp16
__device__ __align__(16) __half d_h1x[52428800];    // [512b][20y][20x][256] fp16
__device__ __align__(16) __half d_w2pk[5308416];    // [81 kxy][256co][256ci] fp16
__device__ __align__(16) float  d_u[4718592];       // u [512][1152][8]
__device__ __align__(16) __half d_uhat_h[94371840]; // u_hat [512][1152][160] fp16

__device__ __forceinline__ uint32_t smem_u32(const void* p) {
    uint32_t a;
    asm("{ .reg .u64 t; cvta.to.shared.u64 t, %1; cvt.u32.u64 %0, t; }" : "=r"(a) : "l"(p));
    return a;
}
#define SW128(x) ((x) ^ (((x) >> 3) & 0x70))

__device__ __forceinline__ void cp_async16(uint32_t dst, const void* src) {
    asm volatile("cp.async.cg.shared.global [%0], [%1], 16;" :: "r"(dst), "l"(src));
}
#define CP_COMMIT() asm volatile("cp.async.commit_group;" ::: "memory")
#define CP_WAIT1()  asm volatile("cp.async.wait_group 1;" ::: "memory")
#define CP_WAIT0()  asm volatile("cp.async.wait_group 0;" ::: "memory")

#define LDSM4(r, a) asm volatile( \
    "ldmatrix.sync.aligned.m8n8.x4.shared.b16 {%0,%1,%2,%3}, [%4];" \
    : "=r"((r)[0]), "=r"((r)[1]), "=r"((r)[2]), "=r"((r)[3]) : "r"(a))

#define MMA16816(c, a, b0, b1) asm volatile( \
    "mma.sync.aligned.m16n8k16.row.col.f32.f16.f16.f32 " \
    "{%0,%1,%2,%3}, {%4,%5,%6,%7}, {%8,%9}, {%0,%1,%2,%3};" \
    : "+f"((c)[0]), "+f"((c)[1]), "+f"((c)[2]), "+f"((c)[3]) \
    : "r"((a)[0]), "r"((a)[1]), "r"((a)[2]), "r"((a)[3]), "r"(b0), "r"(b1))

// ---------------- fused prep: im2col (1024 blk) + packw1 (128 blk) + packw2 (20736 blk) ----
__global__ __launch_bounds__(256) void prep_kernel(
    const float* __restrict__ in, const float* __restrict__ w1,
    const float* __restrict__ w2)
{
    int bx  = blockIdx.x;
    int tid = threadIdx.x;

    if (bx < 1024) {
        // ---- im2col: A[(b*400+pos)][128], k = ky*9+kx (81 real), 2 pos-halves ----
        int b  = bx >> 1;
        int yh = bx & 1;
        __shared__ __half xs[784];
        for (int t = tid; t < 784; t += 256) xs[t] = __float2half_rn(in[b * 784 + t]);
        __syncthreads();

        int k  = tid & 127;
        int p0 = (tid >> 7) + yh * 200;
        int pend = yh * 200 + 200;
        bool valid = (k < 81);
        int ky = k / 9, kx = k - ky * 9;
        __half zero = __float2half_rn(0.f);
        __half* dst = d_a1col + (size_t)b * 51200 + k;
        for (int pos = p0; pos < pend; pos += 2) {
            int oy = pos / 20, ox = pos - oy * 20;
            dst[pos * 128] = valid ? xs[(oy + ky) * 28 + ox + kx] : zero;
        }
    } else if (bx < 1152) {
        // ---- packw1: [2 kc][256 co][64] fp16 ----
        int idx = (bx - 1024) * 256 + tid;
        int j  = idx & 63;
        int co = (idx >> 6) & 255;
        int kc = idx >> 14;
        int k  = kc * 64 + j;
        d_w1pk[idx] = (k < 81) ? __float2half_rn(w1[co * 81 + k]) : __float2half_rn(0.f);
    } else {
        // ---- packw2: [81][co 256][256 ci] fp16 ----
        int idx = (bx - 1152) * 256 + tid;
        int ci   = idx & 255;
        int co   = (idx >> 8) & 255;
        int kidx = idx >> 16;
        int ky = kidx / 9, kx = kidx - ky * 9;
        float v = w2[((size_t)(co * 256 + ci) * 81) + ky * 9 + kx];
        d_w2pk[(size_t)kidx * 65536 + co * 256 + ci] = __float2half_rn(v);
    }
}

// ---------------- conv1 as HMMA GEMM: D[204800,256] = A[.,128] x B[128,256] ----
__global__ void __launch_bounds__(256, 2) conv1_mma_kernel(const float* __restrict__ b1)
{
    extern __shared__ __align__(1024) char smem[];
    uint32_t sb = smem_u32(smem);
    int tid  = threadIdx.x;
    int lane = tid & 31, wid = tid >> 5;
    int mtile = blockIdx.x >> 1, nhalf = blockIdx.x & 1;
    int wm = wid & 3, wn = wid >> 2;

    int apart = tid & 7;
    uint32_t dstoff[4];
    const __half* asrc[4];
    const __half* bsrc[4];
#pragma unroll
    for (int k = 0; k < 4; k++) {
        int r = (tid >> 3) + 32 * k;
        dstoff[k] = SW128((uint32_t)(r * 128 + apart * 16));
        asrc[k] = d_a1col + (size_t)(mtile * 128 + r) * 128 + apart * 8;
        bsrc[k] = d_w1pk + (nhalf * 128 + r) * 64 + apart * 8;
    }

    int rA = wm * 32 + ((lane >> 3) & 1) * 8 + (lane & 7);
    uint32_t aoff0 = (uint32_t)(rA * 128);
    uint32_t keyA = rA & 7, colA = (lane >> 4) & 1;
    int rB = wn * 64 + ((lane >> 4) & 1) * 8 + (lane & 7);
    uint32_t boff0 = (uint32_t)(rB * 128);
    uint32_t keyB = rB & 7, colB = (lane >> 3) & 1;

    float acc[2][8][4];
#pragma unroll
    for (int s = 0; s < 2; s++)
#pragma unroll
        for (int nf = 0; nf < 8; nf++)
#pragma unroll
            for (int e = 0; e < 4; e++) acc[s][nf][e] = 0.f;

#pragma unroll
    for (int kc = 0; kc < 2; kc++) {
        uint32_t abuf = sb + kc * 32768;
        uint32_t bbuf = abuf + 16384;
#pragma unroll
        for (int k = 0; k < 4; k++) {
            cp_async16(abuf + dstoff[k], asrc[k] + kc * 64);
            cp_async16(bbuf + dstoff[k], bsrc[k] + kc * 16384);
        }
        CP_COMMIT();
    }
    CP_WAIT0();
    __syncthreads();

#pragma unroll
    for (int kc = 0; kc < 2; kc++) {
        uint32_t abuf = sb + kc * 32768;
        uint32_t bbuf = abuf + 16384;
#pragma unroll
        for (int kk = 0; kk < 4; kk++) {
            uint32_t a0[4], a1[4];
            uint32_t ca = (((uint32_t)(kk * 2) + colA) ^ keyA) << 4;
            LDSM4(a0, abuf + aoff0 + ca);
            LDSM4(a1, abuf + aoff0 + 2048 + ca);
            uint32_t cb = (((uint32_t)(kk * 2) + colB) ^ keyB) << 4;
#pragma unroll
            for (int p = 0; p < 4; p++) {
                uint32_t bfr[4];
                LDSM4(bfr, bbuf + boff0 + p * 2048 + cb);
                MMA16816(acc[0][2 * p],     a0, bfr[0], bfr[1]);
                MMA16816(acc[0][2 * p + 1], a0, bfr[2], bfr[3]);
                MMA16816(acc[1][2 * p],     a1, bfr[0], bfr[1]);
                MMA16816(acc[1][2 * p + 1], a1, bfr[2], bfr[3]);
            }
        }
    }

    int co0 = nhalf * 128 + wn * 64 + (lane & 3) * 2;
    float bias0[8], bias1[8];
#pragma unroll
    for (int nf = 0; nf < 8; nf++) {
        float2 bv = *(const float2*)(b1 + co0 + nf * 8);
        bias0[nf] = bv.x; bias1[nf] = bv.y;
    }
#pragma unroll
    for (int s = 0; s < 2; s++) {
#pragma unroll
        for (int h = 0; h < 2; h++) {
            int m = mtile * 128 + wm * 32 + s * 16 + (lane >> 2) + h * 8;
            __half* ptr = d_h1x + (size_t)m * 256 + co0;
#pragma unroll
            for (int nf = 0; nf < 8; nf++) {
                float o0 = fmaxf(acc[s][nf][h * 2 + 0] + bias0[nf], 0.f);
                float o1 = fmaxf(acc[s][nf][h * 2 + 1] + bias1[nf], 0.f);
                *(__half2*)(ptr + nf * 8) = __floats2half2_rn(o0, o1);
            }
        }
    }
}

// ---------------- conv2 as HMMA implicit GEMM ----------------
// grid = 288 (144 M-tiles x 2 N-halves), 256 threads (8 warps of 32x64),
// 2 blocks/SM. 324 K-chunks of 64; 3-buffer pipeline, ONE sync per chunk,
// compute FIRST then stage (R15 ordering — measured best).
__global__ void __launch_bounds__(256, 2) conv2_mma_kernel(const float* __restrict__ b2)
{
    extern __shared__ __align__(1024) char smem[];
    uint32_t sb = smem_u32(smem);
    int tid  = threadIdx.x;
    int lane = tid & 31, wid = tid >> 5;
    int mtile = blockIdx.x >> 1, nhalf = blockIdx.x & 1;
    int wm = wid & 3, wn = wid >> 2;

    int apart = tid & 7;
    uint32_t dstoff[4];
    int rowbase[4];
    size_t bsrcoff[4];
#pragma unroll
    for (int k = 0; k < 4; k++) {
        int r = (tid >> 3) + 32 * k;
        dstoff[k] = SW128((uint32_t)(r * 128 + apart * 16));
        int m = mtile * 128 + r;
        int bb = m / 36, pos = m - bb * 36;
        int oy = pos / 6, ox = pos - oy * 6;
        rowbase[k] = bb * 400 + oy * 40 + ox * 2;
        bsrcoff[k] = (size_t)(nhalf * 128 + r) * 256 + apart * 8;
    }

    int rA = wm * 32 + ((lane >> 3) & 1) * 8 + (lane & 7);
    uint32_t aoff0 = (uint32_t)(rA * 128);
    uint32_t keyA = rA & 7, colA = (lane >> 4) & 1;
    int rB = wn * 64 + ((lane >> 4) & 1) * 8 + (lane & 7);
    uint32_t boff0 = (uint32_t)(rB * 128);
    uint32_t keyB = rB & 7, colB = (lane >> 3) & 1;

    float acc[2][8][4];
#pragma unroll
    for (int s = 0; s < 2; s++)
#pragma unroll
        for (int nf = 0; nf < 8; nf++)
#pragma unroll
            for (int e = 0; e < 4; e++) acc[s][nf][e] = 0.f;

    // stage chunk c into buffer buf (A 128x64 = 16KB, B 128x64 = 16KB)
    auto stage = [&](int c, int buf) {
        uint32_t abuf = sb + buf * 32768;
        uint32_t bbuf = abuf + 16384;
        int kidx = c >> 2, cc = c & 3;
        int ky = kidx / 9;
        int koff = ky * 20 + (kidx - ky * 9);
        int ci0 = cc << 6;
        const __half* bsrc = d_w2pk + (size_t)kidx * 65536 + ci0;
#pragma unroll
        for (int k = 0; k < 4; k++) {
            const void* as = d_h1x + (size_t)(rowbase[k] + koff) * 256 + ci0 + apart * 8;
            cp_async16(abuf + dstoff[k], as);
            cp_async16(bbuf + dstoff[k], bsrc + bsrcoff[k]);
        }
    };

    stage(0, 0); CP_COMMIT();
    stage(1, 1); CP_COMMIT();

    int buf = 0;
    for (int c = 0; c < 324; c++) {
        if (c + 2 < 324) { CP_WAIT1(); } else { CP_WAIT0(); }
        __syncthreads();

        uint32_t abuf = sb + buf * 32768;
        uint32_t bbuf = abuf + 16384;
#pragma unroll
        for (int kk = 0; kk < 4; kk++) {
            uint32_t a0[4], a1[4];
            uint32_t ca = (((uint32_t)(kk * 2) + colA) ^ keyA) << 4;
            LDSM4(a0, abuf + aoff0 + ca);
            LDSM4(a1, abuf + aoff0 + 2048 + ca);
            uint32_t cb = (((uint32_t)(kk * 2) + colB) ^ keyB) << 4;
#pragma unroll
            for (int p = 0; p < 4; p++) {
                uint32_t bfr[4];
                LDSM4(bfr, bbuf + boff0 + p * 2048 + cb);
                MMA16816(acc[0][2 * p],     a0, bfr[0], bfr[1]);
                MMA16816(acc[0][2 * p + 1], a0, bfr[2], bfr[3]);
                MMA16816(acc[1][2 * p],     a1, bfr[0], bfr[1]);
                MMA16816(acc[1][2 * p + 1], a1, bfr[2], bfr[3]);
            }
        }

        if (c + 2 < 324) {
            int bn = buf + 2; if (bn >= 3) bn -= 3;
            stage(c + 2, bn);
            CP_COMMIT();
        }
        buf = (buf == 2) ? 0 : buf + 1;
    }

    // ---- epilogue: bias add + scattered float2 stores into transposed u ----
    int co0 = nhalf * 128 + wn * 64 + (lane & 3) * 2;
    float bias0[8], bias1[8];
#pragma unroll
    for (int nf = 0; nf < 8; nf++) {
        float2 bv = *(const float2*)(b2 + co0 + nf * 8);
        bias0[nf] = bv.x; bias1[nf] = bv.y;
    }
#pragma unroll
    for (int s = 0; s < 2; s++) {
        int m0 = mtile * 128 + wm * 32 + s * 16 + (lane >> 2);
#pragma unroll
        for (int h = 0; h < 2; h++) {
            int m = m0 + h * 8;
            int bb = m / 36, pos = m - bb * 36;
            int oy = pos / 6, ox = pos - oy * 6;
            float* ptr = d_u + (size_t)bb * 9216 + ox * 1536 + oy * 256 + co0;
#pragma unroll
            for (int nf = 0; nf < 8; nf++) {
                float2 o;
                o.x = acc[s][nf][h * 2 + 0] + bias0[nf];
                o.y = acc[s][nf][h * 2 + 1] + bias1[nf];
                *(float2*)(ptr + nf * 8) = o;
            }
        }
    }
}

// ---------------- u_hat kernel: block = capsule i, W loaded once, fp16 out ----
__global__ __launch_bounds__(160) void uhat_kernel(const float* __restrict__ capW)
{
    int i   = blockIdx.x;
    int tid = threadIdx.x;
    __shared__ __align__(16) float Ws[1280];
    __shared__ __align__(16) float us[4096];

    for (int t = tid; t < 1280; t += 160) Ws[t] = capW[(size_t)i * 1280 + t];
    for (int t = tid; t < 4096; t += 160) {
        int b = t >> 3, p = t & 7;
        us[t] = d_u[(size_t)b * 9216 + i * 8 + p];
    }
    __syncthreads();

    float wreg[8];
    int off = (tid >> 4) * 128 + (tid & 15);
#pragma unroll
    for (int p = 0; p < 8; p++) wreg[p] = Ws[off + p * 16];

    __half* dst = d_uhat_h + (size_t)i * 160 + tid;
#pragma unroll 4
    for (int b = 0; b < 512; b++) {
        const float4* uq = (const float4*)&us[b * 8];
        float4 x0 = uq[0], x1 = uq[1];
        float a = x0.x * wreg[0] + x0.y * wreg[1] + x0.z * wreg[2] + x0.w * wreg[3]
                + x1.x * wreg[4] + x1.y * wreg[5] + x1.z * wreg[6] + x1.w * wreg[7];
        dst[(size_t)b * 184320] = __float2half_rn(a);
    }
}

// ---------------- fused dynamic routing: 3 uhat passes (fp16), per-batch block ----
__global__ __launch_bounds__(640) void caps_kernel(float* __restrict__ outp)
{
    extern __shared__ float smf[];
    float* bs   = smf;             // [1152*10]
    float* red  = bs + 11520;      // [20*160]
    float* sv   = red + 3200;      // [160]
    float* coef = sv + 160;        // [16]

    int tid  = threadIdx.x;
    int b    = blockIdx.x;
    int lane = tid & 31, warp = tid >> 5, hl = lane >> 4;
    const __half* ub = d_uhat_h + (size_t)b * 184320;

    float sacc[5];

    auto reduce_squash = [&](float scale) {
        __syncthreads();
#pragma unroll
        for (int r = 0; r < 5; r++) red[warp * 160 + lane + 32 * r] = sacc[r];
        __syncthreads();
        if (tid < 160) {
            float s = 0.f;
#pragma unroll
            for (int w = 0; w < 20; w++) s += red[w * 160 + tid];
            sv[tid] = s * scale;
        }
        __syncthreads();
        if (tid < 10) {
            float sq = 0.f;
#pragma unroll
            for (int q = 0; q < 16; q++) { float v = sv[tid * 16 + q]; sq += v * v; }
            coef[tid] = sq * rsqrtf(sq + EPS_SQ) / (1.f + sq);
        }
        __syncthreads();
        if (tid < 160) sv[tid] = coef[tid >> 4] * sv[tid];
        __syncthreads();
    };

    // ---- pass 0: c = 1/10 uniform (i-loop unrolled x2) ----
#pragma unroll
    for (int r = 0; r < 5; r++) sacc[r] = 0.f;
    {
        int i = warp;
        for (; i + 20 < 1152; i += 40) {
            const __half* up0 = ub + (size_t)i * 160;
            const __half* up1 = ub + (size_t)(i + 20) * 160;
#pragma unroll
            for (int r = 0; r < 5; r++)
                sacc[r] += __half2float(up0[lane + 32 * r]) + __half2float(up1[lane + 32 * r]);
        }
        if (i < 1152) {
            const __half* up = ub + (size_t)i * 160;
#pragma unroll
            for (int r = 0; r < 5; r++) sacc[r] += __half2float(up[lane + 32 * r]);
        }
    }
    reduce_squash(0.1f);

    // ---- passes 1, 2: fused b-update + softmax + s-accumulate (unrolled x2) ----
#pragma unroll 1
    for (int pass = 1; pass <= 2; pass++) {
        float vreg[5];
#pragma unroll
        for (int r = 0; r < 5; r++) vreg[r] = sv[lane + 32 * r];
#pragma unroll
        for (int r = 0; r < 5; r++) sacc[r] = 0.f;

        auto body = [&](int i) {
            const __half* up = ub + (size_t)i * 160;
            float uh[5], d[5];
#pragma unroll
            for (int r = 0; r < 5; r++) uh[r] = __half2float(up[lane + 32 * r]);
#pragma unroll
            for (int r = 0; r < 5; r++) d[r] = uh[r] * vreg[r];
#pragma unroll
            for (int mk = 8; mk; mk >>= 1)
#pragma unroll
                for (int r = 0; r < 5; r++) d[r] += __shfl_xor_sync(0xffffffffu, d[r], mk);

            float bnew[5];
            if (pass == 1) {
#pragma unroll
                for (int r = 0; r < 5; r++) bnew[r] = d[r];
                if ((lane & 15) == 0) {
#pragma unroll
                    for (int r = 0; r < 5; r++) bs[i * 10 + 2 * r + hl] = bnew[r];
                }
            } else {
#pragma unroll
                for (int r = 0; r < 5; r++) bnew[r] = bs[i * 10 + 2 * r + hl] + d[r];
            }

            float m1 = bnew[0];
#pragma unroll
            for (int r = 1; r < 5; r++) m1 = fmaxf(m1, bnew[r]);
            m1 = fmaxf(m1, __shfl_xor_sync(0xffffffffu, m1, 16));
            float e[5], ss = 0.f;
#pragma unroll
            for (int r = 0; r < 5; r++) { e[r] = __expf(bnew[r] - m1); ss += e[r]; }
            ss += __shfl_xor_sync(0xffffffffu, ss, 16);
            float inv = 1.f / ss;
#pragma unroll
            for (int r = 0; r < 5; r++) sacc[r] += e[r] * inv * uh[r];
        };

        int i = warp;
        for (; i + 20 < 1152; i += 40) { body(i); body(i + 20); }
        if (i < 1152) body(i);

        reduce_squash(1.0f);
    }

    if (tid < 160) outp[b * 160 + tid] = sv[tid];
}

// ---------------- launch ----------------
extern "C" void kernel_launch(void* const* d_in, const int* in_sizes, int n_in,
                              void* d_out, int out_size)
{
    const float* inp = (const float*)d_in[0];
    const float* w1  = (const float*)d_in[1];
    const float* b1  = (const float*)d_in[2];
    const float* w2  = (const float*)d_in[3];
    const float* b2  = (const float*)d_in[4];
    const float* cw  = (const float*)d_in[5];
    float* outp = (float*)d_out;

    prep_kernel<<<21888, 256>>>(inp, w1, w2);

    cudaFuncSetAttribute(conv1_mma_kernel, cudaFuncAttributeMaxDynamicSharedMemorySize, 65536);
    conv1_mma_kernel<<<3200, 256, 65536>>>(b1);

    cudaFuncSetAttribute(conv2_mma_kernel, cudaFuncAttributeMaxDynamicSharedMemorySize, 98304);
    conv2_mma_kernel<<<288, 256, 98304>>>(b2);

    uhat_kernel<<<1152, 160>>>(cw);

    const int caps_smem = (11520 + 3200 + 160 + 16) * 4;   // 59584 B
    cudaFuncSetAttribute(caps_kernel, cudaFuncAttributeMaxDynamicSharedMemorySize, caps_smem);
    caps_kernel<<<512, 640, caps_smem>>>(outp);
}